// round 1
// baseline (speedup 1.0000x reference)
#include <cuda_runtime.h>
#include <math.h>
#include <stdint.h>

// Problem constants
#define BB 4
#define LL 2048
#define DD 1024
#define NH 16
#define DK 64
#define MD ((size_t)BB*LL*DD)      // 8388608 elems per [B,L,D] tensor
#define MLE ((size_t)BB*LL*LL)     // 16777216 mask / attn_mean elems

// ---------------- scratch (allocation-free: __device__ globals) ----------------
__device__ float g_q[(size_t)BB*LL*DD];
__device__ float g_k[(size_t)BB*LL*DD];
__device__ float g_v[(size_t)BB*LL*DD];
__device__ float g_x[(size_t)BB*LL*DD];                 // pre-LN (out-proj + residual)
__device__ unsigned char g_mask[(size_t)BB*LL*LL];      // canonical 0/1 mask
__device__ float g_s[(size_t)BB*NH*LL*LL];              // scores -> probs
__device__ int g_mask_mode;                             // 0=u8, 1=i32, 2=f32

// ---------------- mask dtype probe + canonicalization ----------------
__global__ void probe_mask_kernel(const void* mask) {
    if (threadIdx.x == 0 && blockIdx.x == 0) {
        const unsigned int* w = (const unsigned int*)mask;
        int nf = 0, ni = 0;
        for (int i = 0; i < 1024; i++) {
            unsigned int v = w[i];
            if (v == 0x3F800000u) nf++;
            else if (v == 1u) ni++;
        }
        g_mask_mode = (nf > 256) ? 2 : ((ni > 256) ? 1 : 0);
    }
}

__global__ void convert_mask_kernel(const void* mask) {
    size_t i = (size_t)blockIdx.x * blockDim.x + threadIdx.x;
    int mode = g_mask_mode;
    unsigned char v;
    if (mode == 0)      v = (((const unsigned char*)mask)[i] != 0);
    else if (mode == 1) v = (((const int*)mask)[i] != 0);
    else                v = (((const float*)mask)[i] != 0.0f);
    g_mask[i] = v;
}

// ---------------- generic projection GEMM: C = A @ W^T + bias (+ resid) ----------------
// A: [8192,1024] row-major, W: [1024,1024] row-major (torch Linear weight),
// C selected by `which`: 0->g_q, 1->g_k, 2->g_v, 3->g_x (with residual).
__global__ void gemm_proj_kernel(const float* __restrict__ A,
                                 const float* __restrict__ W,
                                 const float* __restrict__ bias,
                                 const float* __restrict__ resid,
                                 int which)
{
    float* C = (which == 0) ? g_q : (which == 1) ? g_k : (which == 2) ? g_v : g_x;
    __shared__ float As[16][65];   // [k][m]
    __shared__ float Ws[16][65];   // [k][n]
    const int tid = threadIdx.x;
    const int tx = tid & 15, ty = tid >> 4;
    const int m0 = blockIdx.y * 64, n0 = blockIdx.x * 64;
    const int lm = tid >> 2;          // 0..63
    const int lk = (tid & 3) * 4;     // 0,4,8,12

    float acc[4][4] = {};
    for (int kt = 0; kt < DD; kt += 16) {
        float4 av = *(const float4*)(A + (size_t)(m0 + lm) * DD + kt + lk);
        float4 wv = *(const float4*)(W + (size_t)(n0 + lm) * DD + kt + lk);
        As[lk+0][lm] = av.x; As[lk+1][lm] = av.y; As[lk+2][lm] = av.z; As[lk+3][lm] = av.w;
        Ws[lk+0][lm] = wv.x; Ws[lk+1][lm] = wv.y; Ws[lk+2][lm] = wv.z; Ws[lk+3][lm] = wv.w;
        __syncthreads();
        #pragma unroll
        for (int k = 0; k < 16; k++) {
            float a[4], w[4];
            #pragma unroll
            for (int u = 0; u < 4; u++) { a[u] = As[k][ty*4+u]; w[u] = Ws[k][tx*4+u]; }
            #pragma unroll
            for (int i = 0; i < 4; i++)
                #pragma unroll
                for (int j = 0; j < 4; j++)
                    acc[i][j] += a[i] * w[j];
        }
        __syncthreads();
    }
    #pragma unroll
    for (int i = 0; i < 4; i++) {
        int m = m0 + ty*4 + i;
        #pragma unroll
        for (int j = 0; j < 4; j++) {
            int n = n0 + tx*4 + j;
            float v = acc[i][j] + bias[n];
            if (resid) v += resid[(size_t)m * DD + n];
            C[(size_t)m * DD + n] = v;
        }
    }
}

// ---------------- scores: S[b,h,q,k] = scale * <q_row, k_row> ; masked -> -1e9 ----------------
__global__ void scores_kernel() {
    const int bh = blockIdx.z;
    const int b = bh >> 4, h = bh & 15;
    const int q0 = blockIdx.y * 64, k0 = blockIdx.x * 64;
    __shared__ float Qs[64][65];   // [d][q]
    __shared__ float Ks[64][65];   // [d][k]
    const int tid = threadIdx.x;
    const int tx = tid & 15, ty = tid >> 4;

    for (int i = tid; i < 64*64; i += 256) {
        int row = i >> 6, col = i & 63;
        Qs[col][row] = g_q[((size_t)b*LL + q0 + row) * DD + h*DK + col];
        Ks[col][row] = g_k[((size_t)b*LL + k0 + row) * DD + h*DK + col];
    }
    __syncthreads();

    float acc[4][4] = {};
    #pragma unroll 4
    for (int d = 0; d < 64; d++) {
        float qv[4], kv[4];
        #pragma unroll
        for (int u = 0; u < 4; u++) { qv[u] = Qs[d][ty*4+u]; kv[u] = Ks[d][tx*4+u]; }
        #pragma unroll
        for (int i = 0; i < 4; i++)
            #pragma unroll
            for (int j = 0; j < 4; j++)
                acc[i][j] += qv[i] * kv[j];
    }

    const float scale = 0.125f;   // 1/sqrt(64)
    #pragma unroll
    for (int i = 0; i < 4; i++) {
        int q = q0 + ty*4 + i;
        #pragma unroll
        for (int j = 0; j < 4; j++) {
            int k = k0 + tx*4 + j;
            float s = acc[i][j] * scale;
            if (g_mask[(size_t)b*LL*LL + (size_t)q*LL + k]) s = -1e9f;
            g_s[((size_t)bh*LL + q) * LL + k] = s;
        }
    }
}

// ---------------- softmax per (b,h,q) row + fused attn_mean (mean over heads) ----------------
__global__ void softmax_kernel(float* __restrict__ am_out) {
    const int q = blockIdx.x, b = blockIdx.y;
    const int tid = threadIdx.x;
    __shared__ float red[256];
    float am[8] = {};
    for (int h = 0; h < NH; h++) {
        float* row = g_s + ((size_t)(b*NH + h) * LL + q) * LL;
        float v[8]; float mx = -3.4e38f;
        #pragma unroll
        for (int u = 0; u < 8; u++) { v[u] = row[u*256 + tid]; mx = fmaxf(mx, v[u]); }
        red[tid] = mx; __syncthreads();
        for (int s2 = 128; s2 > 0; s2 >>= 1) {
            if (tid < s2) red[tid] = fmaxf(red[tid], red[tid + s2]);
            __syncthreads();
        }
        mx = red[0]; __syncthreads();
        float sum = 0.f;
        #pragma unroll
        for (int u = 0; u < 8; u++) { v[u] = __expf(v[u] - mx); sum += v[u]; }
        red[tid] = sum; __syncthreads();
        for (int s2 = 128; s2 > 0; s2 >>= 1) {
            if (tid < s2) red[tid] += red[tid + s2];
            __syncthreads();
        }
        float inv = 1.0f / red[0]; __syncthreads();
        #pragma unroll
        for (int u = 0; u < 8; u++) {
            float p = v[u] * inv;
            row[u*256 + tid] = p;
            am[u] += p;
        }
    }
    float* am_row = am_out + ((size_t)b*LL + q) * LL;
    #pragma unroll
    for (int u = 0; u < 8; u++) am_row[u*256 + tid] = am[u] * (1.0f / NH);
}

// ---------------- context: C[b,q,h*64+j] = sum_k P[b,h,q,k] * V[b,k,h*64+j] ----------------
__global__ void av_kernel(float* __restrict__ ctx) {
    const int bh = blockIdx.y;
    const int b = bh >> 4, h = bh & 15;
    const int q0 = blockIdx.x * 64;
    __shared__ float Ps[64][65];   // [i][k]
    __shared__ float Vs[64][65];   // [k][j]
    const int tid = threadIdx.x;
    const int tx = tid & 15, ty = tid >> 4;

    float acc[4][4] = {};
    for (int kt = 0; kt < LL; kt += 64) {
        for (int i = tid; i < 64*64; i += 256) {
            int row = i >> 6, col = i & 63;
            Ps[row][col] = g_s[((size_t)bh*LL + q0 + row) * LL + kt + col];
            Vs[row][col] = g_v[((size_t)b*LL + kt + row) * DD + h*DK + col];
        }
        __syncthreads();
        #pragma unroll 4
        for (int k = 0; k < 64; k++) {
            float p[4], vv[4];
            #pragma unroll
            for (int u = 0; u < 4; u++) { p[u] = Ps[ty*4+u][k]; vv[u] = Vs[k][tx*4+u]; }
            #pragma unroll
            for (int i = 0; i < 4; i++)
                #pragma unroll
                for (int j = 0; j < 4; j++)
                    acc[i][j] += p[i] * vv[j];
        }
        __syncthreads();
    }
    #pragma unroll
    for (int i = 0; i < 4; i++)
        #pragma unroll
        for (int j = 0; j < 4; j++)
            ctx[((size_t)b*LL + q0 + ty*4 + i) * DD + h*DK + tx*4 + j] = acc[i][j];
}

// ---------------- LayerNorm over last dim of g_x -> out ----------------
__global__ void ln_kernel(const float* __restrict__ gamma,
                          const float* __restrict__ beta,
                          float* __restrict__ out) {
    const int row = blockIdx.x;
    const int tid = threadIdx.x;
    const float* x = g_x + (size_t)row * DD;
    __shared__ float red[256];
    float v[4]; float s = 0.f;
    #pragma unroll
    for (int u = 0; u < 4; u++) { v[u] = x[u*256 + tid]; s += v[u]; }
    red[tid] = s; __syncthreads();
    for (int s2 = 128; s2 > 0; s2 >>= 1) {
        if (tid < s2) red[tid] += red[tid + s2];
        __syncthreads();
    }
    float mean = red[0] * (1.0f / DD); __syncthreads();
    float sq = 0.f;
    #pragma unroll
    for (int u = 0; u < 4; u++) { float d = v[u] - mean; sq += d * d; }
    red[tid] = sq; __syncthreads();
    for (int s2 = 128; s2 > 0; s2 >>= 1) {
        if (tid < s2) red[tid] += red[tid + s2];
        __syncthreads();
    }
    float var = red[0] * (1.0f / DD);
    float inv = rsqrtf(var + 1e-5f);
    #pragma unroll
    for (int u = 0; u < 4; u++) {
        int c = u*256 + tid;
        out[(size_t)row * DD + c] = (v[u] - mean) * inv * gamma[c] + beta[c];
    }
}

// ---------------- launch ----------------
extern "C" void kernel_launch(void* const* d_in, const int* in_sizes, int n_in,
                              void* d_out, int out_size) {
    const float* Q    = (const float*)d_in[0];
    const float* K_   = (const float*)d_in[1];
    const float* V    = (const float*)d_in[2];
    const void*  mask = d_in[3];
    const float* Wq   = (const float*)d_in[4];
    const float* bq   = (const float*)d_in[5];
    const float* Wk   = (const float*)d_in[6];
    const float* bk   = (const float*)d_in[7];
    const float* Wv   = (const float*)d_in[8];
    const float* bv   = (const float*)d_in[9];
    const float* Wo   = (const float*)d_in[10];
    const float* bo   = (const float*)d_in[11];
    const float* gamma= (const float*)d_in[12];
    const float* beta = (const float*)d_in[13];

    float* out = (float*)d_out;            // [B,L,D]   layernorm output
    float* ctx = out + MD;                 // [B,L,D]   context
    float* am  = out + 2*MD;               // [B,L,L]   attn mean over heads

    // canonicalize mask (dtype-robust)
    probe_mask_kernel<<<1, 32>>>(mask);
    convert_mask_kernel<<<(int)(MLE / 256), 256>>>(mask);

    dim3 gproj(DD/64, (BB*LL)/64);         // (16,128)
    gemm_proj_kernel<<<gproj, 256>>>(Q,  Wq, bq, nullptr, 0);
    gemm_proj_kernel<<<gproj, 256>>>(K_, Wk, bk, nullptr, 1);
    gemm_proj_kernel<<<gproj, 256>>>(V,  Wv, bv, nullptr, 2);

    scores_kernel<<<dim3(LL/64, LL/64, BB*NH), 256>>>();
    softmax_kernel<<<dim3(LL, BB), 256>>>(am);
    av_kernel<<<dim3(LL/64, BB*NH), 256>>>(ctx);

    gemm_proj_kernel<<<gproj, 256>>>(ctx, Wo, bo, Q, 3);   // out-proj + bias + residual -> g_x
    ln_kernel<<<BB*LL, 256>>>(gamma, beta, out);
}

// round 2
// speedup vs baseline: 1.4470x; 1.4470x over previous
#include <cuda_runtime.h>
#include <math.h>
#include <stdint.h>

// Problem constants
#define BB 4
#define LL 2048
#define DD 1024
#define NH 16
#define DK 64
#define MD ((size_t)BB*LL*DD)
#define MLE ((size_t)BB*LL*LL)

// ---------------- scratch (allocation-free: __device__ globals) ----------------
__device__ float g_q[(size_t)BB*LL*DD];
__device__ float g_k[(size_t)BB*LL*DD];
__device__ float g_v[(size_t)BB*LL*DD];
__device__ float g_x[(size_t)BB*LL*DD];                 // pre-LN (out-proj + residual)
__device__ unsigned char g_mask[(size_t)BB*LL*LL];      // canonical 0/1 mask
__device__ float g_s[(size_t)BB*NH*LL*LL];              // scores -> probs
__device__ int g_mask_mode;

// ---------------- mask dtype probe + canonicalization ----------------
__global__ void probe_mask_kernel(const void* mask) {
    if (threadIdx.x == 0 && blockIdx.x == 0) {
        const unsigned int* w = (const unsigned int*)mask;
        int nf = 0, ni = 0;
        for (int i = 0; i < 1024; i++) {
            unsigned int v = w[i];
            if (v == 0x3F800000u) nf++;
            else if (v == 1u) ni++;
        }
        g_mask_mode = (nf > 256) ? 2 : ((ni > 256) ? 1 : 0);
    }
}

__global__ void convert_mask_kernel(const void* mask) {
    size_t i = (size_t)blockIdx.x * blockDim.x + threadIdx.x;
    int mode = g_mask_mode;
    unsigned char v;
    if (mode == 0)      v = (((const unsigned char*)mask)[i] != 0);
    else if (mode == 1) v = (((const int*)mask)[i] != 0);
    else                v = (((const float*)mask)[i] != 0.0f);
    g_mask[i] = v;
}

// ---------------- projection GEMM: C = A @ W^T + bias (+ resid) ----------------
// 128x128 block tile, 256 threads, 8x8 per-thread register tile, K-tile 16.
__global__ __launch_bounds__(256)
void gemm_proj_kernel(const float* __restrict__ A,
                      const float* __restrict__ W,
                      const float* __restrict__ bias,
                      const float* __restrict__ resid,
                      int which)
{
    float* C = (which == 0) ? g_q : (which == 1) ? g_k : (which == 2) ? g_v : g_x;
    __shared__ float As[16][132];   // [k][m]
    __shared__ float Ws[16][132];   // [k][n]
    const int tid = threadIdx.x;
    const int tx = tid & 15, ty = tid >> 4;
    const int m0 = blockIdx.y * 128, n0 = blockIdx.x * 128;
    const int lr = tid >> 1;            // 0..127
    const int lc = (tid & 1) * 8;       // 0 or 8

    float acc[8][8] = {};
    for (int kt = 0; kt < DD; kt += 16) {
        float4 a0 = *(const float4*)(A + (size_t)(m0 + lr) * DD + kt + lc);
        float4 a1 = *(const float4*)(A + (size_t)(m0 + lr) * DD + kt + lc + 4);
        float4 w0 = *(const float4*)(W + (size_t)(n0 + lr) * DD + kt + lc);
        float4 w1 = *(const float4*)(W + (size_t)(n0 + lr) * DD + kt + lc + 4);
        As[lc+0][lr]=a0.x; As[lc+1][lr]=a0.y; As[lc+2][lr]=a0.z; As[lc+3][lr]=a0.w;
        As[lc+4][lr]=a1.x; As[lc+5][lr]=a1.y; As[lc+6][lr]=a1.z; As[lc+7][lr]=a1.w;
        Ws[lc+0][lr]=w0.x; Ws[lc+1][lr]=w0.y; Ws[lc+2][lr]=w0.z; Ws[lc+3][lr]=w0.w;
        Ws[lc+4][lr]=w1.x; Ws[lc+5][lr]=w1.y; Ws[lc+6][lr]=w1.z; Ws[lc+7][lr]=w1.w;
        __syncthreads();
        #pragma unroll
        for (int k = 0; k < 16; k++) {
            float4 aa0 = *(const float4*)&As[k][ty*8];
            float4 aa1 = *(const float4*)&As[k][ty*8+4];
            float4 ww0 = *(const float4*)&Ws[k][tx*8];
            float4 ww1 = *(const float4*)&Ws[k][tx*8+4];
            float a[8] = {aa0.x,aa0.y,aa0.z,aa0.w,aa1.x,aa1.y,aa1.z,aa1.w};
            float w[8] = {ww0.x,ww0.y,ww0.z,ww0.w,ww1.x,ww1.y,ww1.z,ww1.w};
            #pragma unroll
            for (int i = 0; i < 8; i++)
                #pragma unroll
                for (int j = 0; j < 8; j++)
                    acc[i][j] += a[i] * w[j];
        }
        __syncthreads();
    }
    #pragma unroll
    for (int i = 0; i < 8; i++) {
        int m = m0 + ty*8 + i;
        #pragma unroll
        for (int jv = 0; jv < 2; jv++) {
            int n = n0 + tx*8 + jv*4;
            float4 r;
            r.x = acc[i][jv*4+0] + bias[n+0];
            r.y = acc[i][jv*4+1] + bias[n+1];
            r.z = acc[i][jv*4+2] + bias[n+2];
            r.w = acc[i][jv*4+3] + bias[n+3];
            if (resid) {
                float4 rv = *(const float4*)(resid + (size_t)m * DD + n);
                r.x += rv.x; r.y += rv.y; r.z += rv.z; r.w += rv.w;
            }
            *(float4*)(C + (size_t)m * DD + n) = r;
        }
    }
}

// ---------------- scores: S = scale * Q_h K_h^T ; masked -> -1e9 ----------------
// 128x128 tile per block, 256 threads, 8x8 per thread, d-loop in chunks of 16.
__global__ __launch_bounds__(256)
void scores_kernel() {
    const int bh = blockIdx.z;
    const int b = bh >> 4, h = bh & 15;
    const int q0 = blockIdx.y * 128, k0 = blockIdx.x * 128;
    __shared__ float Qs[16][132];   // [d][q]
    __shared__ float Ks[16][132];   // [d][k]
    const int tid = threadIdx.x;
    const int tx = tid & 15, ty = tid >> 4;
    const int lr = tid >> 1;
    const int lc = (tid & 1) * 8;

    float acc[8][8] = {};
    for (int dt = 0; dt < DK; dt += 16) {
        float4 q0v = *(const float4*)(g_q + ((size_t)b*LL + q0 + lr) * DD + h*DK + dt + lc);
        float4 q1v = *(const float4*)(g_q + ((size_t)b*LL + q0 + lr) * DD + h*DK + dt + lc + 4);
        float4 k0v = *(const float4*)(g_k + ((size_t)b*LL + k0 + lr) * DD + h*DK + dt + lc);
        float4 k1v = *(const float4*)(g_k + ((size_t)b*LL + k0 + lr) * DD + h*DK + dt + lc + 4);
        Qs[lc+0][lr]=q0v.x; Qs[lc+1][lr]=q0v.y; Qs[lc+2][lr]=q0v.z; Qs[lc+3][lr]=q0v.w;
        Qs[lc+4][lr]=q1v.x; Qs[lc+5][lr]=q1v.y; Qs[lc+6][lr]=q1v.z; Qs[lc+7][lr]=q1v.w;
        Ks[lc+0][lr]=k0v.x; Ks[lc+1][lr]=k0v.y; Ks[lc+2][lr]=k0v.z; Ks[lc+3][lr]=k0v.w;
        Ks[lc+4][lr]=k1v.x; Ks[lc+5][lr]=k1v.y; Ks[lc+6][lr]=k1v.z; Ks[lc+7][lr]=k1v.w;
        __syncthreads();
        #pragma unroll
        for (int d = 0; d < 16; d++) {
            float4 qa0 = *(const float4*)&Qs[d][ty*8];
            float4 qa1 = *(const float4*)&Qs[d][ty*8+4];
            float4 ka0 = *(const float4*)&Ks[d][tx*8];
            float4 ka1 = *(const float4*)&Ks[d][tx*8+4];
            float qv[8] = {qa0.x,qa0.y,qa0.z,qa0.w,qa1.x,qa1.y,qa1.z,qa1.w};
            float kv[8] = {ka0.x,ka0.y,ka0.z,ka0.w,ka1.x,ka1.y,ka1.z,ka1.w};
            #pragma unroll
            for (int i = 0; i < 8; i++)
                #pragma unroll
                for (int j = 0; j < 8; j++)
                    acc[i][j] += qv[i] * kv[j];
        }
        __syncthreads();
    }

    const float scale = 0.125f;
    #pragma unroll
    for (int i = 0; i < 8; i++) {
        int q = q0 + ty*8 + i;
        const unsigned char* mrow = g_mask + (size_t)b*LL*LL + (size_t)q*LL;
        float* srow = g_s + ((size_t)bh*LL + q) * LL;
        #pragma unroll
        for (int jv = 0; jv < 2; jv++) {
            int k = k0 + tx*8 + jv*4;
            float4 r;
            r.x = mrow[k+0] ? -1e9f : acc[i][jv*4+0] * scale;
            r.y = mrow[k+1] ? -1e9f : acc[i][jv*4+1] * scale;
            r.z = mrow[k+2] ? -1e9f : acc[i][jv*4+2] * scale;
            r.w = mrow[k+3] ? -1e9f : acc[i][jv*4+3] * scale;
            *(float4*)(srow + k) = r;
        }
    }
}

// ---------------- softmax per (b,q) over all heads, fused attn_mean ----------------
__global__ __launch_bounds__(256)
void softmax_kernel(float* __restrict__ am_out) {
    const int q = blockIdx.x, b = blockIdx.y;
    const int tid = threadIdx.x;
    const int lane = tid & 31, wid = tid >> 5;
    __shared__ float redA[8], redB[8];
    float4 am0 = {0,0,0,0}, am1 = {0,0,0,0};
    for (int h = 0; h < NH; h++) {
        float* row = g_s + ((size_t)(b*NH + h) * LL + q) * LL;
        float4 v0 = ((const float4*)row)[tid];
        float4 v1 = ((const float4*)row)[tid + 256];
        float mx = fmaxf(fmaxf(fmaxf(v0.x,v0.y),fmaxf(v0.z,v0.w)),
                         fmaxf(fmaxf(v1.x,v1.y),fmaxf(v1.z,v1.w)));
        #pragma unroll
        for (int o = 16; o; o >>= 1) mx = fmaxf(mx, __shfl_xor_sync(~0u, mx, o));
        if (lane == 0) redA[wid] = mx;
        __syncthreads();
        mx = redA[0];
        #pragma unroll
        for (int w = 1; w < 8; w++) mx = fmaxf(mx, redA[w]);
        v0.x = __expf(v0.x - mx); v0.y = __expf(v0.y - mx);
        v0.z = __expf(v0.z - mx); v0.w = __expf(v0.w - mx);
        v1.x = __expf(v1.x - mx); v1.y = __expf(v1.y - mx);
        v1.z = __expf(v1.z - mx); v1.w = __expf(v1.w - mx);
        float sum = v0.x+v0.y+v0.z+v0.w+v1.x+v1.y+v1.z+v1.w;
        #pragma unroll
        for (int o = 16; o; o >>= 1) sum += __shfl_xor_sync(~0u, sum, o);
        if (lane == 0) redB[wid] = sum;
        __syncthreads();
        sum = redB[0];
        #pragma unroll
        for (int w = 1; w < 8; w++) sum += redB[w];
        float inv = 1.0f / sum;
        v0.x *= inv; v0.y *= inv; v0.z *= inv; v0.w *= inv;
        v1.x *= inv; v1.y *= inv; v1.z *= inv; v1.w *= inv;
        ((float4*)row)[tid] = v0;
        ((float4*)row)[tid + 256] = v1;
        am0.x += v0.x; am0.y += v0.y; am0.z += v0.z; am0.w += v0.w;
        am1.x += v1.x; am1.y += v1.y; am1.z += v1.z; am1.w += v1.w;
    }
    const float s = 1.0f / NH;
    am0.x*=s; am0.y*=s; am0.z*=s; am0.w*=s;
    am1.x*=s; am1.y*=s; am1.z*=s; am1.w*=s;
    float* am_row = am_out + ((size_t)b*LL + q) * LL;
    ((float4*)am_row)[tid] = am0;
    ((float4*)am_row)[tid + 256] = am1;
}

// ---------------- context: C[b,q,h*64+j] = sum_k P[b,h,q,k] * V[b,k,h*64+j] ----------------
// 128(q) x 64(j) tile, 128 threads, 8x8 per thread, k-tile 16.
__global__ __launch_bounds__(128)
void av_kernel(float* __restrict__ ctx) {
    const int bh = blockIdx.y;
    const int b = bh >> 4, h = bh & 15;
    const int q0 = blockIdx.x * 128;
    __shared__ float Ps[16][132];   // [k][q]
    __shared__ float Vs[16][68];    // [k][j]
    const int tid = threadIdx.x;
    const int tx = tid & 7, ty = tid >> 3;       // tx: 8 j-groups, ty: 16 q-groups
    const int vr = tid >> 3, vc = (tid & 7) * 8; // V loader: 16 rows x 64 cols

    float acc[8][8] = {};
    for (int kt = 0; kt < LL; kt += 16) {
        // P: 128 q-rows x 16 k  (each thread: its own q-row, 4 float4)
        const float* prow = g_s + ((size_t)bh*LL + q0 + tid) * LL + kt;
        float4 p0 = *(const float4*)(prow + 0);
        float4 p1 = *(const float4*)(prow + 4);
        float4 p2 = *(const float4*)(prow + 8);
        float4 p3 = *(const float4*)(prow + 12);
        Ps[0][tid]=p0.x;  Ps[1][tid]=p0.y;  Ps[2][tid]=p0.z;  Ps[3][tid]=p0.w;
        Ps[4][tid]=p1.x;  Ps[5][tid]=p1.y;  Ps[6][tid]=p1.z;  Ps[7][tid]=p1.w;
        Ps[8][tid]=p2.x;  Ps[9][tid]=p2.y;  Ps[10][tid]=p2.z; Ps[11][tid]=p2.w;
        Ps[12][tid]=p3.x; Ps[13][tid]=p3.y; Ps[14][tid]=p3.z; Ps[15][tid]=p3.w;
        // V: 16 k-rows x 64 j  (each thread: 2 float4)
        const float* vrow = g_v + ((size_t)b*LL + kt + vr) * DD + h*DK + vc;
        float4 vv0 = *(const float4*)(vrow + 0);
        float4 vv1 = *(const float4*)(vrow + 4);
        *(float4*)&Vs[vr][vc]   = vv0;
        *(float4*)&Vs[vr][vc+4] = vv1;
        __syncthreads();
        #pragma unroll
        for (int k = 0; k < 16; k++) {
            float4 pa0 = *(const float4*)&Ps[k][ty*8];
            float4 pa1 = *(const float4*)&Ps[k][ty*8+4];
            float4 va0 = *(const float4*)&Vs[k][tx*8];
            float4 va1 = *(const float4*)&Vs[k][tx*8+4];
            float p[8] = {pa0.x,pa0.y,pa0.z,pa0.w,pa1.x,pa1.y,pa1.z,pa1.w};
            float v[8] = {va0.x,va0.y,va0.z,va0.w,va1.x,va1.y,va1.z,va1.w};
            #pragma unroll
            for (int i = 0; i < 8; i++)
                #pragma unroll
                for (int j = 0; j < 8; j++)
                    acc[i][j] += p[i] * v[j];
        }
        __syncthreads();
    }
    #pragma unroll
    for (int i = 0; i < 8; i++) {
        #pragma unroll
        for (int jv = 0; jv < 2; jv++) {
            float4 r = {acc[i][jv*4+0], acc[i][jv*4+1], acc[i][jv*4+2], acc[i][jv*4+3]};
            *(float4*)(ctx + ((size_t)b*LL + q0 + ty*8 + i) * DD + h*DK + tx*8 + jv*4) = r;
        }
    }
}

// ---------------- LayerNorm over last dim of g_x -> out ----------------
__global__ __launch_bounds__(256)
void ln_kernel(const float* __restrict__ gamma,
               const float* __restrict__ beta,
               float* __restrict__ out) {
    const int row = blockIdx.x;
    const int tid = threadIdx.x;
    const int lane = tid & 31, wid = tid >> 5;
    const float* x = g_x + (size_t)row * DD;
    __shared__ float redA[8], redB[8];
    float4 v = ((const float4*)x)[tid];
    float s = v.x + v.y + v.z + v.w;
    #pragma unroll
    for (int o = 16; o; o >>= 1) s += __shfl_xor_sync(~0u, s, o);
    if (lane == 0) redA[wid] = s;
    __syncthreads();
    s = redA[0];
    #pragma unroll
    for (int w = 1; w < 8; w++) s += redA[w];
    float mean = s * (1.0f / DD);
    float dx = v.x-mean, dy = v.y-mean, dz = v.z-mean, dw = v.w-mean;
    float sq = dx*dx + dy*dy + dz*dz + dw*dw;
    #pragma unroll
    for (int o = 16; o; o >>= 1) sq += __shfl_xor_sync(~0u, sq, o);
    if (lane == 0) redB[wid] = sq;
    __syncthreads();
    sq = redB[0];
    #pragma unroll
    for (int w = 1; w < 8; w++) sq += redB[w];
    float inv = rsqrtf(sq * (1.0f / DD) + 1e-5f);
    int c = tid * 4;
    float4 g = ((const float4*)gamma)[tid];
    float4 be = ((const float4*)beta)[tid];
    float4 r;
    r.x = dx * inv * g.x + be.x;
    r.y = dy * inv * g.y + be.y;
    r.z = dz * inv * g.z + be.z;
    r.w = dw * inv * g.w + be.w;
    *(float4*)(out + (size_t)row * DD + c) = r;
}

// ---------------- launch ----------------
extern "C" void kernel_launch(void* const* d_in, const int* in_sizes, int n_in,
                              void* d_out, int out_size) {
    const float* Q    = (const float*)d_in[0];
    const float* K_   = (const float*)d_in[1];
    const float* V    = (const float*)d_in[2];
    const void*  mask = d_in[3];
    const float* Wq   = (const float*)d_in[4];
    const float* bq   = (const float*)d_in[5];
    const float* Wk   = (const float*)d_in[6];
    const float* bk   = (const float*)d_in[7];
    const float* Wv   = (const float*)d_in[8];
    const float* bv   = (const float*)d_in[9];
    const float* Wo   = (const float*)d_in[10];
    const float* bo   = (const float*)d_in[11];
    const float* gamma= (const float*)d_in[12];
    const float* beta = (const float*)d_in[13];

    float* out = (float*)d_out;            // [B,L,D]   layernorm output
    float* ctx = out + MD;                 // [B,L,D]   context
    float* am  = out + 2*MD;               // [B,L,L]   attn mean over heads

    probe_mask_kernel<<<1, 32>>>(mask);
    convert_mask_kernel<<<(int)(MLE / 256), 256>>>(mask);

    dim3 gproj(DD/128, (BB*LL)/128);       // (8, 64)
    gemm_proj_kernel<<<gproj, 256>>>(Q,  Wq, bq, nullptr, 0);
    gemm_proj_kernel<<<gproj, 256>>>(K_, Wk, bk, nullptr, 1);
    gemm_proj_kernel<<<gproj, 256>>>(V,  Wv, bv, nullptr, 2);

    scores_kernel<<<dim3(LL/128, LL/128, BB*NH), 256>>>();
    softmax_kernel<<<dim3(LL, BB), 256>>>(am);
    av_kernel<<<dim3(LL/128, BB*NH), 128>>>(ctx);

    gemm_proj_kernel<<<gproj, 256>>>(ctx, Wo, bo, Q, 3);   // out-proj + residual -> g_x
    ln_kernel<<<BB*LL, 256>>>(gamma, beta, out);
}